// round 6
// baseline (speedup 1.0000x reference)
#include <cuda_runtime.h>
#include <math.h>

#define N_USERS 50000
#define N_ENT   150000
#define NNODES  200000
#define D       64
#define NEDGE   3200000
#define BATCH   4096
#define NSLOTS  8192
#define CE_CAP  400000

// -------- scratch (device globals; no allocation allowed) --------
__device__ unsigned g_flag[(NNODES + 31) / 32];    // needed-dst bitset (25 KB)
__device__ int      g_slot[NNODES];                // node -> dense slot (valid iff flagged)
__device__ int      g_uniq[NSLOTS];                // slot -> node
__device__ int      g_nuniq;
__device__ int      g_nce;
__device__ int      g_cnt[NSLOTS];                 // per-slot stored-edge count
__device__ int      g_off[NSLOTS + 1];             // bucket offsets
__device__ int      g_pos[NSLOTS];                 // bucket cursors
__device__ int      g_ce_src[CE_CAP];
__device__ int      g_ce_slot[CE_CAP];
__device__ int      g_bin_src[CE_CAP];             // srcs grouped by dst slot
__device__ float    g_hd[(size_t)NSLOTS * D];      // dense h_out (2 MB, L2-resident)
__device__ float    g_v1[D], g_v2[D];
__device__ float    g_c1, g_c2;

__device__ __forceinline__ const float2* feat2(int n, const float* ue, const float* ee) {
    return (n < N_USERS) ? (const float2*)ue + (size_t)n * 32
                         : (const float2*)ee + (size_t)(n - N_USERS) * 32;
}

// -------- K0: zero flags/counters/counts + compute v1,v2,c1,c2 --------
__global__ void k_init(const float* __restrict__ Wa, const float* __restrict__ ba,
                       const float* __restrict__ a) {
    int tid = blockIdx.x * blockDim.x + threadIdx.x;
    int stride = gridDim.x * blockDim.x;
    const int NW = (NNODES + 31) / 32;
    for (int i = tid; i < NW; i += stride) g_flag[i] = 0u;
    for (int i = tid; i < NSLOTS; i += stride) g_cnt[i] = 0;
    if (tid == 0) { g_nuniq = 0; g_nce = 0; }
    if (blockIdx.x == 0) {
        int k = threadIdx.x;
        if (k < D) {
            float v1 = 0.f, v2 = 0.f;
            for (int j = 0; j < D; j++) {
                float w = Wa[k * D + j];
                v1 += w * a[j];
                v2 += w * a[D + j];
            }
            g_v1[k] = v1; g_v2[k] = v2;
        }
        if (k == 0) {
            float c1 = 0.f, c2 = 0.f;
            for (int j = 0; j < D; j++) { c1 += ba[j] * a[j]; c2 += ba[j] * a[D + j]; }
            g_c1 = c1; g_c2 = c2;
        }
    }
}

// -------- K1: mark needed nodes, assign dense slots --------
__global__ void k_mark(const int* __restrict__ uid, const int* __restrict__ iid) {
    int i = blockIdx.x * blockDim.x + threadIdx.x;
    if (i >= 2 * BATCH) return;
    int node = (i < BATCH) ? uid[i] : N_USERS + iid[i - BATCH];
    unsigned bit = 1u << (node & 31);
    unsigned old = atomicOr(&g_flag[node >> 5], bit);
    if (!(old & bit)) {
        int slot = atomicAdd(&g_nuniq, 1);
        g_slot[node] = slot;
        g_uniq[slot] = node;
    }
}

// -------- K2: edge stream — flag test, warp-aggregated compaction + per-slot count --------
// Scalar idx loads (same pattern as both previously passing kernels); NO block barriers.
__global__ void __launch_bounds__(256) k_edge1(const int* __restrict__ idx) {
    int gt = blockIdx.x * blockDim.x + threadIdx.x;
    int stride = gridDim.x * blockDim.x;
    int lane = threadIdx.x & 31;
    int iters = (NEDGE + stride - 1) / stride;    // uniform trip count for all warps
    for (int it = 0; it < iters; ++it) {
        int e = gt + it * stride;
        bool v = (e < NEDGE);
        int src = 0, dst = 0;
        if (v) {
            src = idx[e];
            dst = idx[NEDGE + e];
        }
        bool take = v && ((g_flag[dst >> 5] >> (dst & 31)) & 1u);
        unsigned m = __ballot_sync(0xFFFFFFFFu, take);
        if (m) {
            int base = 0;
            if (lane == 0) base = atomicAdd(&g_nce, __popc(m));
            base = __shfl_sync(0xFFFFFFFFu, base, 0);
            if (take) {
                int pos = base + __popc(m & ((1u << lane) - 1u));
                if (pos < CE_CAP) {
                    int slot = g_slot[dst];
                    atomicAdd(&g_cnt[slot], 1);   // count only stored edges
                    g_ce_src[pos] = src;
                    g_ce_slot[pos] = slot;
                }
            }
        }
    }
}

// -------- K3: exclusive scan of bucket counts (single block) --------
__global__ void k_scan() {
    __shared__ int part[256];
    int t = threadIdx.x;
    const int PER = NSLOTS / 256;   // 32
    int base = t * PER;
    int s = 0;
    for (int i = 0; i < PER; i++) s += g_cnt[base + i];
    part[t] = s;
    __syncthreads();
    for (int d = 1; d < 256; d <<= 1) {
        int v = (t >= d) ? part[t - d] : 0;
        __syncthreads();
        part[t] += v;
        __syncthreads();
    }
    int run = (t == 0) ? 0 : part[t - 1];
    for (int i = 0; i < PER; i++) {
        g_off[base + i] = run;
        g_pos[base + i] = run;
        run += g_cnt[base + i];
    }
    if (t == 255) g_off[NSLOTS] = part[255];
}

// -------- K4: scatter compacted edges into per-dst buckets --------
__global__ void k_bin() {
    int nce = g_nce;
    if (nce > CE_CAP) nce = CE_CAP;
    int gt = blockIdx.x * blockDim.x + threadIdx.x;
    int stride = gridDim.x * blockDim.x;
    for (int i = gt; i < nce; i += stride) {
        int slot = g_ce_slot[i];
        int pos = atomicAdd(&g_pos[slot], 1);
        g_bin_src[pos] = g_ce_src[i];
    }
}

// -------- K5: warp-per-dst gather + fused epilogue (attention, W1/W2, normalize) --------
__global__ void __launch_bounds__(256) k_gather(const float* __restrict__ ue, const float* __restrict__ ee,
                                                const float* __restrict__ W1, const float* __restrict__ b1,
                                                const float* __restrict__ W2, const float* __restrict__ b2) {
    __shared__ float sW1[D * D], sW2[D * D], sb1[D], sb2[D];
    __shared__ float sg[8][D];
    int tid = threadIdx.x, lane = tid & 31, wid = tid >> 5;
    for (int i = tid; i < D * D; i += 256) { sW1[i] = W1[i]; sW2[i] = W2[i]; }
    for (int i = tid; i < D; i += 256) { sb1[i] = b1[i]; sb2[i] = b2[i]; }
    __syncthreads();
    float2 v1 = ((const float2*)g_v1)[lane];
    float2 v2 = ((const float2*)g_v2)[lane];
    float c1 = g_c1, c2 = g_c2;
    int nu = g_nuniq;
    int wg = (blockIdx.x * blockDim.x + tid) >> 5;
    int nwarps = (gridDim.x * blockDim.x) >> 5;
    for (int q = wg; q < nu; q += nwarps) {
        int n = g_uniq[q];
        float2 hs = feat2(n, ue, ee)[lane];
        // s2 of dst from its own row (needed anyway as h_self)
        float p = hs.x * v2.x + hs.y * v2.y;
        #pragma unroll
        for (int o = 16; o; o >>= 1) p += __shfl_xor_sync(0xFFFFFFFFu, p, o);
        float s2d = p + c2;
        int eb = g_off[q], ee_ = g_off[q + 1];
        float ax = 0.f, ay = 0.f, den = 0.f;
        #pragma unroll 2
        for (int e = eb; e < ee_; e++) {
            int src = g_bin_src[e];                     // warp-broadcast load
            float2 f = feat2(src, ue, ee)[lane];
            float pp = f.x * v1.x + f.y * v1.y;         // s1[src] on the fly
            #pragma unroll
            for (int o = 16; o; o >>= 1) pp += __shfl_xor_sync(0xFFFFFFFFu, pp, o);
            float ev = pp + c1 + s2d;
            ev = (ev > 0.f) ? ev : 0.2f * ev;
            float ex = __expf(ev);
            den += ex;
            ax += ex * f.x;
            ay += ex * f.y;
        }
        float inv = 1.f / (den + 1e-9f);
        float sden = den * inv;
        __syncwarp();
        sg[wid][2 * lane] = ax * inv;
        sg[wid][2 * lane + 1] = ay * inv;
        __syncwarp();
        float n0 = sden * sb1[2 * lane], n1 = sden * sb1[2 * lane + 1];
        #pragma unroll 16
        for (int k = 0; k < D; k++) {
            float gk = sg[wid][k];
            float2 wr = ((const float2*)(sW1 + k * D))[lane];
            n0 += gk * wr.x; n1 += gk * wr.y;
        }
        float sum0 = hs.x + n0, sum1 = hs.y + n1;
        float p0 = hs.x * n0, p1 = hs.y * n1;
        __syncwarp();
        sg[wid][2 * lane] = p0;
        sg[wid][2 * lane + 1] = p1;
        __syncwarp();
        float z0 = sum0 + sb2[2 * lane], z1 = sum1 + sb2[2 * lane + 1];
        #pragma unroll 16
        for (int k = 0; k < D; k++) {
            float pk = sg[wid][k];
            float2 wr = ((const float2*)(sW2 + k * D))[lane];
            z0 += pk * wr.x; z1 += pk * wr.y;
        }
        float h0 = (z0 > 0.f) ? z0 : 0.2f * z0;
        float h1 = (z1 > 0.f) ? z1 : 0.2f * z1;
        float ss = h0 * h0 + h1 * h1;
        #pragma unroll
        for (int o = 16; o; o >>= 1) ss += __shfl_xor_sync(0xFFFFFFFFu, ss, o);
        float invn = 1.f / fmaxf(sqrtf(ss), 1e-12f);
        float* orow = g_hd + (size_t)q * D;
        orow[2 * lane] = h0 * invn;
        orow[2 * lane + 1] = h1 * invn;
    }
}

// -------- K6: final pair dots (dense h_out via slot map) --------
__global__ void k_final(const int* __restrict__ uid, const int* __restrict__ iid,
                        const float* __restrict__ ue, const float* __restrict__ ee,
                        float* __restrict__ out) {
    int lane = threadIdx.x & 31;
    int wg = (blockIdx.x * blockDim.x + threadIdx.x) >> 5;
    int nwarps = (gridDim.x * blockDim.x) >> 5;
    for (int p = wg; p < BATCH; p += nwarps) {
        int un = uid[p];
        int in = N_USERS + iid[p];
        float2 fu = feat2(un, ue, ee)[lane];
        float2 fi = feat2(in, ue, ee)[lane];
        float acc = fu.x * fi.x + fu.y * fi.y;
        int su = g_slot[un], si = g_slot[in];
        float2 hu = ((const float2*)(g_hd + (size_t)su * D))[lane];
        float2 hi = ((const float2*)(g_hd + (size_t)si * D))[lane];
        acc += hu.x * hi.x + hu.y * hi.y;
        #pragma unroll
        for (int o = 16; o; o >>= 1) acc += __shfl_xor_sync(0xFFFFFFFFu, acc, o);
        if (lane == 0) out[p] = acc;
    }
}

extern "C" void kernel_launch(void* const* d_in, const int* in_sizes, int n_in,
                              void* d_out, int out_size) {
    const int* idx = (const int*)d_in[0];
    const int* uid = (const int*)d_in[1];
    const int* iid = (const int*)d_in[2];
    int base = (in_sizes[3] <= 2) ? 4 : 3;   // skip num_nodes scalar if present
    const float* ue = (const float*)d_in[base + 0];
    const float* ee = (const float*)d_in[base + 1];
    const float* Wa = (const float*)d_in[base + 2];
    const float* ba = (const float*)d_in[base + 3];
    const float* W1 = (const float*)d_in[base + 4];
    const float* b1 = (const float*)d_in[base + 5];
    const float* W2 = (const float*)d_in[base + 6];
    const float* b2 = (const float*)d_in[base + 7];
    const float* a  = (const float*)d_in[base + 8];
    float* out = (float*)d_out;
    (void)n_in; (void)out_size;

    k_init<<<40, 256>>>(Wa, ba, a);
    k_mark<<<32, 256>>>(uid, iid);
    k_edge1<<<2048, 256>>>(idx);
    k_scan<<<1, 256>>>();
    k_bin<<<256, 256>>>();
    k_gather<<<1024, 256>>>(ue, ee, W1, b1, W2, b2);
    k_final<<<64, 256>>>(uid, iid, ue, ee, out);
}

// round 7
// speedup vs baseline: 2.1395x; 2.1395x over previous
#include <cuda_runtime.h>
#include <math.h>

#define N_USERS 50000
#define N_ENT   150000
#define NNODES  200000
#define D       64
#define NEDGE   3200000
#define BATCH   4096
#define NSLOTS  8192
#define CAP     128        // per-slot bucket capacity (Poisson(16): P(deg>128) ~ 1e-80)
#define OV_CAP  8192

// -------- scratch (device globals; no allocation allowed) --------
__device__ unsigned g_flag[(NNODES + 31) / 32];    // needed-dst bitset (25 KB)
__device__ int      g_slot[NNODES];                // node -> dense slot (valid iff flagged)
__device__ int      g_uniq[NSLOTS];                // slot -> node
__device__ int      g_nuniq;
__device__ int      g_cnt[NSLOTS];                 // per-slot taken-edge count
__device__ int      g_bin[NSLOTS * CAP];           // fixed-stride src buckets (4 MB)
__device__ int      g_nov;
__device__ int      g_ov_src[OV_CAP];
__device__ int      g_ov_slot[OV_CAP];
__device__ float    g_ovden[NSLOTS];               // overflow contributions (normally 0)
__device__ float    g_ovacc[NSLOTS * D];           // 2 MB
__device__ float    g_hd[NSLOTS * D];              // dense h_out (2 MB, L2-resident)
__device__ float    g_v1[D], g_v2[D];
__device__ float    g_c1, g_c2;

__device__ __forceinline__ const float2* feat2(int n, const float* ue, const float* ee) {
    return (n < N_USERS) ? (const float2*)ue + (size_t)n * 32
                         : (const float2*)ee + (size_t)(n - N_USERS) * 32;
}

// -------- K0: zero scratch + compute v1,v2,c1,c2 --------
__global__ void k_init(const float* __restrict__ Wa, const float* __restrict__ ba,
                       const float* __restrict__ a) {
    int tid = blockIdx.x * blockDim.x + threadIdx.x;
    int stride = gridDim.x * blockDim.x;
    const int NW = (NNODES + 31) / 32;
    for (int i = tid; i < NW; i += stride) g_flag[i] = 0u;
    for (int i = tid; i < NSLOTS; i += stride) { g_cnt[i] = 0; g_ovden[i] = 0.f; }
    float4* ov4 = (float4*)g_ovacc;
    for (int i = tid; i < NSLOTS * D / 4; i += stride) ov4[i] = make_float4(0.f, 0.f, 0.f, 0.f);
    if (tid == 0) { g_nuniq = 0; g_nov = 0; }
    if (blockIdx.x == 0) {
        int k = threadIdx.x;
        if (k < D) {
            float v1 = 0.f, v2 = 0.f;
            for (int j = 0; j < D; j++) {
                float w = Wa[k * D + j];
                v1 += w * a[j];
                v2 += w * a[D + j];
            }
            g_v1[k] = v1; g_v2[k] = v2;
        }
        if (k == 0) {
            float c1 = 0.f, c2 = 0.f;
            for (int j = 0; j < D; j++) { c1 += ba[j] * a[j]; c2 += ba[j] * a[D + j]; }
            g_c1 = c1; g_c2 = c2;
        }
    }
}

// -------- K1: mark needed nodes, assign dense slots --------
__global__ void k_mark(const int* __restrict__ uid, const int* __restrict__ iid) {
    int i = blockIdx.x * blockDim.x + threadIdx.x;
    if (i >= 2 * BATCH) return;
    int node = (i < BATCH) ? uid[i] : N_USERS + iid[i - BATCH];
    unsigned bit = 1u << (node & 31);
    unsigned old = atomicOr(&g_flag[node >> 5], bit);
    if (!(old & bit)) {
        int slot = atomicAdd(&g_nuniq, 1);
        g_slot[node] = slot;
        g_uniq[slot] = node;
    }
}

// -------- K2: edge stream — flag test + direct scatter into fixed-stride buckets --------
__global__ void __launch_bounds__(256) k_edge1(const int* __restrict__ idx) {
    int gt = blockIdx.x * blockDim.x + threadIdx.x;
    int stride = gridDim.x * blockDim.x;
    for (int e = gt; e < NEDGE; e += stride) {
        int dst = idx[NEDGE + e];
        if ((g_flag[dst >> 5] >> (dst & 31)) & 1u) {
            int src = idx[e];
            int slot = g_slot[dst];
            int pos = atomicAdd(&g_cnt[slot], 1);
            if (pos < CAP) {
                g_bin[slot * CAP + pos] = src;
            } else {
                int op = atomicAdd(&g_nov, 1);
                if (op < OV_CAP) { g_ov_src[op] = src; g_ov_slot[op] = slot; }
            }
        }
    }
}

// -------- K3: overflow edges (normally zero) — warp per edge, atomic accumulate --------
__global__ void k_ov(const float* __restrict__ ue, const float* __restrict__ ee) {
    int nov = g_nov;
    if (nov > OV_CAP) nov = OV_CAP;
    if (nov == 0) return;
    int lane = threadIdx.x & 31;
    int wg = (blockIdx.x * blockDim.x + threadIdx.x) >> 5;
    int nwarps = (gridDim.x * blockDim.x) >> 5;
    float2 v1 = ((const float2*)g_v1)[lane];
    float2 v2 = ((const float2*)g_v2)[lane];
    float c1 = g_c1, c2 = g_c2;
    for (int i = wg; i < nov; i += nwarps) {
        int src = g_ov_src[i];
        int slot = g_ov_slot[i];
        int dstn = g_uniq[slot];
        float2 hd = feat2(dstn, ue, ee)[lane];
        float pd = hd.x * v2.x + hd.y * v2.y;
        float2 f = feat2(src, ue, ee)[lane];
        float ps = f.x * v1.x + f.y * v1.y;
        #pragma unroll
        for (int o = 16; o; o >>= 1) {
            pd += __shfl_xor_sync(0xFFFFFFFFu, pd, o);
            ps += __shfl_xor_sync(0xFFFFFFFFu, ps, o);
        }
        float ev = ps + c1 + pd + c2;
        ev = (ev > 0.f) ? ev : 0.2f * ev;
        float ex = __expf(ev);
        atomicAdd(&g_ovacc[slot * D + 2 * lane],     ex * f.x);
        atomicAdd(&g_ovacc[slot * D + 2 * lane + 1], ex * f.y);
        if (lane == 0) atomicAdd(&g_ovden[slot], ex);
    }
}

// -------- K4: warp-per-dst gather + fused epilogue (paired edges for ILP) --------
__global__ void __launch_bounds__(256) k_gather(const float* __restrict__ ue, const float* __restrict__ ee,
                                                const float* __restrict__ W1, const float* __restrict__ b1,
                                                const float* __restrict__ W2, const float* __restrict__ b2) {
    __shared__ float sW1[D * D], sW2[D * D], sb1[D], sb2[D];
    __shared__ float sg[8][D];
    int tid = threadIdx.x, lane = tid & 31, wid = tid >> 5;
    for (int i = tid; i < D * D; i += 256) { sW1[i] = W1[i]; sW2[i] = W2[i]; }
    for (int i = tid; i < D; i += 256) { sb1[i] = b1[i]; sb2[i] = b2[i]; }
    __syncthreads();
    float2 v1 = ((const float2*)g_v1)[lane];
    float2 v2 = ((const float2*)g_v2)[lane];
    float c1 = g_c1, c2 = g_c2;
    int nu = g_nuniq;
    int wg = (blockIdx.x * blockDim.x + tid) >> 5;
    int nwarps = (gridDim.x * blockDim.x) >> 5;
    for (int q = wg; q < nu; q += nwarps) {
        int n = g_uniq[q];
        float2 hs = feat2(n, ue, ee)[lane];
        float p = hs.x * v2.x + hs.y * v2.y;   // s2[dst] from its own row
        #pragma unroll
        for (int o = 16; o; o >>= 1) p += __shfl_xor_sync(0xFFFFFFFFu, p, o);
        float s2d = p + c2;
        int deg = g_cnt[q];
        if (deg > CAP) deg = CAP;
        const int* bs = g_bin + q * CAP;
        float ax = 0.f, ay = 0.f, den = 0.f;
        int e = 0;
        for (; e + 1 < deg; e += 2) {          // two interleaved reduction chains
            int s0 = bs[e], s1i = bs[e + 1];
            float2 f0 = feat2(s0, ue, ee)[lane];
            float2 f1 = feat2(s1i, ue, ee)[lane];
            float p0 = f0.x * v1.x + f0.y * v1.y;
            float p1 = f1.x * v1.x + f1.y * v1.y;
            #pragma unroll
            for (int o = 16; o; o >>= 1) {
                p0 += __shfl_xor_sync(0xFFFFFFFFu, p0, o);
                p1 += __shfl_xor_sync(0xFFFFFFFFu, p1, o);
            }
            float e0 = p0 + c1 + s2d; e0 = (e0 > 0.f) ? e0 : 0.2f * e0;
            float e1 = p1 + c1 + s2d; e1 = (e1 > 0.f) ? e1 : 0.2f * e1;
            float x0 = __expf(e0), x1 = __expf(e1);
            den += x0 + x1;
            ax += x0 * f0.x + x1 * f1.x;
            ay += x0 * f0.y + x1 * f1.y;
        }
        if (e < deg) {
            int s0 = bs[e];
            float2 f0 = feat2(s0, ue, ee)[lane];
            float p0 = f0.x * v1.x + f0.y * v1.y;
            #pragma unroll
            for (int o = 16; o; o >>= 1) p0 += __shfl_xor_sync(0xFFFFFFFFu, p0, o);
            float e0 = p0 + c1 + s2d; e0 = (e0 > 0.f) ? e0 : 0.2f * e0;
            float x0 = __expf(e0);
            den += x0; ax += x0 * f0.x; ay += x0 * f0.y;
        }
        // fold in overflow contributions (normally zero)
        den += g_ovden[q];
        ax += g_ovacc[q * D + 2 * lane];
        ay += g_ovacc[q * D + 2 * lane + 1];
        float inv = 1.f / (den + 1e-9f);
        float sden = den * inv;
        __syncwarp();
        sg[wid][2 * lane] = ax * inv;
        sg[wid][2 * lane + 1] = ay * inv;
        __syncwarp();
        float n0 = sden * sb1[2 * lane], n1 = sden * sb1[2 * lane + 1];
        #pragma unroll 16
        for (int k = 0; k < D; k++) {
            float gk = sg[wid][k];
            float2 wr = ((const float2*)(sW1 + k * D))[lane];
            n0 += gk * wr.x; n1 += gk * wr.y;
        }
        float sum0 = hs.x + n0, sum1 = hs.y + n1;
        float p0s = hs.x * n0, p1s = hs.y * n1;
        __syncwarp();
        sg[wid][2 * lane] = p0s;
        sg[wid][2 * lane + 1] = p1s;
        __syncwarp();
        float z0 = sum0 + sb2[2 * lane], z1 = sum1 + sb2[2 * lane + 1];
        #pragma unroll 16
        for (int k = 0; k < D; k++) {
            float pk = sg[wid][k];
            float2 wr = ((const float2*)(sW2 + k * D))[lane];
            z0 += pk * wr.x; z1 += pk * wr.y;
        }
        float h0 = (z0 > 0.f) ? z0 : 0.2f * z0;
        float h1 = (z1 > 0.f) ? z1 : 0.2f * z1;
        float ss = h0 * h0 + h1 * h1;
        #pragma unroll
        for (int o = 16; o; o >>= 1) ss += __shfl_xor_sync(0xFFFFFFFFu, ss, o);
        float invn = 1.f / fmaxf(sqrtf(ss), 1e-12f);
        float* orow = g_hd + (size_t)q * D;
        orow[2 * lane] = h0 * invn;
        orow[2 * lane + 1] = h1 * invn;
    }
}

// -------- K5: final pair dots (dense h_out via slot map) --------
__global__ void k_final(const int* __restrict__ uid, const int* __restrict__ iid,
                        const float* __restrict__ ue, const float* __restrict__ ee,
                        float* __restrict__ out) {
    int lane = threadIdx.x & 31;
    int wg = (blockIdx.x * blockDim.x + threadIdx.x) >> 5;
    int nwarps = (gridDim.x * blockDim.x) >> 5;
    for (int p = wg; p < BATCH; p += nwarps) {
        int un = uid[p];
        int in = N_USERS + iid[p];
        float2 fu = feat2(un, ue, ee)[lane];
        float2 fi = feat2(in, ue, ee)[lane];
        float acc = fu.x * fi.x + fu.y * fi.y;
        int su = g_slot[un], si = g_slot[in];
        float2 hu = ((const float2*)(g_hd + (size_t)su * D))[lane];
        float2 hi = ((const float2*)(g_hd + (size_t)si * D))[lane];
        acc += hu.x * hi.x + hu.y * hi.y;
        #pragma unroll
        for (int o = 16; o; o >>= 1) acc += __shfl_xor_sync(0xFFFFFFFFu, acc, o);
        if (lane == 0) out[p] = acc;
    }
}

extern "C" void kernel_launch(void* const* d_in, const int* in_sizes, int n_in,
                              void* d_out, int out_size) {
    const int* idx = (const int*)d_in[0];
    const int* uid = (const int*)d_in[1];
    const int* iid = (const int*)d_in[2];
    int base = (in_sizes[3] <= 2) ? 4 : 3;   // skip num_nodes scalar if present
    const float* ue = (const float*)d_in[base + 0];
    const float* ee = (const float*)d_in[base + 1];
    const float* Wa = (const float*)d_in[base + 2];
    const float* ba = (const float*)d_in[base + 3];
    const float* W1 = (const float*)d_in[base + 4];
    const float* b1 = (const float*)d_in[base + 5];
    const float* W2 = (const float*)d_in[base + 6];
    const float* b2 = (const float*)d_in[base + 7];
    const float* a  = (const float*)d_in[base + 8];
    float* out = (float*)d_out;
    (void)n_in; (void)out_size;

    k_init<<<128, 256>>>(Wa, ba, a);
    k_mark<<<32, 256>>>(uid, iid);
    k_edge1<<<2048, 256>>>(idx);
    k_ov<<<32, 256>>>(ue, ee);
    k_gather<<<1024, 256>>>(ue, ee, W1, b1, W2, b2);
    k_final<<<64, 256>>>(uid, iid, ue, ee, out);
}

// round 9
// speedup vs baseline: 2.2632x; 1.0578x over previous
#include <cuda_runtime.h>
#include <math.h>

#define N_USERS 50000
#define N_ENT   150000
#define NNODES  200000
#define D       64
#define NEDGE   3200000
#define BATCH   4096
#define NSLOTS  8192
#define CAP     128        // per-slot bucket capacity (Poisson(16): P(deg>128) ~ 1e-80)
#define OV_CAP  8192

// -------- scratch (device globals; no allocation allowed) --------
__device__ unsigned g_flag[(NNODES + 31) / 32];    // needed-dst bitset (25 KB)
__device__ int      g_slot[NNODES];                // node -> dense slot (valid iff flagged)
__device__ int      g_uniq[NSLOTS];                // slot -> node
__device__ int      g_nuniq;
__device__ int      g_cnt[NSLOTS];                 // per-slot taken-edge count
__device__ int      g_bin[NSLOTS * CAP];           // fixed-stride src buckets (4 MB)
__device__ int      g_nov;
__device__ int      g_ov_src[OV_CAP];
__device__ int      g_ov_slot[OV_CAP];
__device__ float    g_hd[NSLOTS * D];              // dense h_out (2 MB, L2-resident)
__device__ float    g_v1[D], g_v2[D];
__device__ float    g_c1, g_c2;

__device__ __forceinline__ const float2* feat2(int n, const float* ue, const float* ee) {
    return (n < N_USERS) ? (const float2*)ue + (size_t)n * 32
                         : (const float2*)ee + (size_t)(n - N_USERS) * 32;
}

// -------- K0: zero scratch + compute v1,v2,c1,c2 --------
__global__ void k_init(const float* __restrict__ Wa, const float* __restrict__ ba,
                       const float* __restrict__ a) {
    int tid = blockIdx.x * blockDim.x + threadIdx.x;
    int stride = gridDim.x * blockDim.x;
    const int NW = (NNODES + 31) / 32;
    for (int i = tid; i < NW; i += stride) g_flag[i] = 0u;
    for (int i = tid; i < NSLOTS; i += stride) g_cnt[i] = 0;
    if (tid == 0) { g_nuniq = 0; g_nov = 0; }
    if (blockIdx.x == 0) {
        int k = threadIdx.x;
        if (k < D) {
            float v1 = 0.f, v2 = 0.f;
            for (int j = 0; j < D; j++) {
                float w = Wa[k * D + j];
                v1 += w * a[j];
                v2 += w * a[D + j];
            }
            g_v1[k] = v1; g_v2[k] = v2;
        }
        if (k == 0) {
            float c1 = 0.f, c2 = 0.f;
            for (int j = 0; j < D; j++) { c1 += ba[j] * a[j]; c2 += ba[j] * a[D + j]; }
            g_c1 = c1; g_c2 = c2;
        }
    }
}

// -------- K1: mark needed nodes, assign dense slots --------
__global__ void k_mark(const int* __restrict__ uid, const int* __restrict__ iid) {
    int i = blockIdx.x * blockDim.x + threadIdx.x;
    if (i >= 2 * BATCH) return;
    int node = (i < BATCH) ? uid[i] : N_USERS + iid[i - BATCH];
    unsigned bit = 1u << (node & 31);
    unsigned old = atomicOr(&g_flag[node >> 5], bit);
    if (!(old & bit)) {
        int slot = atomicAdd(&g_nuniq, 1);
        g_slot[node] = slot;
        g_uniq[slot] = node;
    }
}

// -------- K2: edge stream — flag test + direct scatter (identical to R7-passing) --------
__global__ void __launch_bounds__(256) k_edge1(const int* __restrict__ idx) {
    int gt = blockIdx.x * blockDim.x + threadIdx.x;
    int stride = gridDim.x * blockDim.x;
    for (int e = gt; e < NEDGE; e += stride) {
        int dst = idx[NEDGE + e];
        if ((g_flag[dst >> 5] >> (dst & 31)) & 1u) {
            int src = idx[e];
            int slot = g_slot[dst];
            int pos = atomicAdd(&g_cnt[slot], 1);
            if (pos < CAP) {
                g_bin[slot * CAP + pos] = src;
            } else {
                int op = atomicAdd(&g_nov, 1);
                if (op < OV_CAP) { g_ov_src[op] = src; g_ov_slot[op] = slot; }
            }
        }
    }
}

// -------- K3: warp-per-dst gather + fused epilogue (4-way interleaved edges) --------
__global__ void __launch_bounds__(256) k_gather(const float* __restrict__ ue, const float* __restrict__ ee,
                                                const float* __restrict__ W1, const float* __restrict__ b1,
                                                const float* __restrict__ W2, const float* __restrict__ b2) {
    __shared__ float sW1[D * D], sW2[D * D], sb1[D], sb2[D];
    __shared__ float sg[8][D];
    int tid = threadIdx.x, lane = tid & 31, wid = tid >> 5;
    for (int i = tid; i < D * D; i += 256) { sW1[i] = W1[i]; sW2[i] = W2[i]; }
    for (int i = tid; i < D; i += 256) { sb1[i] = b1[i]; sb2[i] = b2[i]; }
    __syncthreads();
    float2 v1 = ((const float2*)g_v1)[lane];
    float2 v2 = ((const float2*)g_v2)[lane];
    float c1 = g_c1, c2 = g_c2;
    int nu = g_nuniq;
    int nov = g_nov;
    if (nov > OV_CAP) nov = OV_CAP;
    int wg = (blockIdx.x * blockDim.x + tid) >> 5;
    int nwarps = (gridDim.x * blockDim.x) >> 5;
    for (int q = wg; q < nu; q += nwarps) {
        int n = g_uniq[q];
        float2 hs = feat2(n, ue, ee)[lane];
        float p = hs.x * v2.x + hs.y * v2.y;   // s2[dst] from its own row
        #pragma unroll
        for (int o = 16; o; o >>= 1) p += __shfl_xor_sync(0xFFFFFFFFu, p, o);
        float s2d = p + c2;
        int deg = g_cnt[q];
        if (deg > CAP) deg = CAP;
        const int* bs = g_bin + q * CAP;
        float ax = 0.f, ay = 0.f, den = 0.f;
        int e = 0;
        for (; e + 3 < deg; e += 4) {          // four interleaved reduction chains
            int s0 = bs[e], s1i = bs[e + 1], s2i = bs[e + 2], s3i = bs[e + 3];
            float2 f0 = feat2(s0,  ue, ee)[lane];
            float2 f1 = feat2(s1i, ue, ee)[lane];
            float2 f2 = feat2(s2i, ue, ee)[lane];
            float2 f3 = feat2(s3i, ue, ee)[lane];
            float p0 = f0.x * v1.x + f0.y * v1.y;
            float p1 = f1.x * v1.x + f1.y * v1.y;
            float p2 = f2.x * v1.x + f2.y * v1.y;
            float p3 = f3.x * v1.x + f3.y * v1.y;
            #pragma unroll
            for (int o = 16; o; o >>= 1) {
                p0 += __shfl_xor_sync(0xFFFFFFFFu, p0, o);
                p1 += __shfl_xor_sync(0xFFFFFFFFu, p1, o);
                p2 += __shfl_xor_sync(0xFFFFFFFFu, p2, o);
                p3 += __shfl_xor_sync(0xFFFFFFFFu, p3, o);
            }
            float e0 = p0 + c1 + s2d; e0 = (e0 > 0.f) ? e0 : 0.2f * e0;
            float e1 = p1 + c1 + s2d; e1 = (e1 > 0.f) ? e1 : 0.2f * e1;
            float e2 = p2 + c1 + s2d; e2 = (e2 > 0.f) ? e2 : 0.2f * e2;
            float e3 = p3 + c1 + s2d; e3 = (e3 > 0.f) ? e3 : 0.2f * e3;
            float x0 = __expf(e0), x1 = __expf(e1), x2 = __expf(e2), x3 = __expf(e3);
            den += (x0 + x1) + (x2 + x3);
            ax += x0 * f0.x + x1 * f1.x + x2 * f2.x + x3 * f3.x;
            ay += x0 * f0.y + x1 * f1.y + x2 * f2.y + x3 * f3.y;
        }
        for (; e < deg; e++) {
            int s0 = bs[e];
            float2 f0 = feat2(s0, ue, ee)[lane];
            float p0 = f0.x * v1.x + f0.y * v1.y;
            #pragma unroll
            for (int o = 16; o; o >>= 1) p0 += __shfl_xor_sync(0xFFFFFFFFu, p0, o);
            float e0 = p0 + c1 + s2d; e0 = (e0 > 0.f) ? e0 : 0.2f * e0;
            float x0 = __expf(e0);
            den += x0; ax += x0 * f0.x; ay += x0 * f0.y;
        }
        // overflow edges (normally nov == 0): direct scan
        for (int i = 0; i < nov; i++) {
            if (g_ov_slot[i] == q) {
                int s0 = g_ov_src[i];
                float2 f0 = feat2(s0, ue, ee)[lane];
                float p0 = f0.x * v1.x + f0.y * v1.y;
                #pragma unroll
                for (int o = 16; o; o >>= 1) p0 += __shfl_xor_sync(0xFFFFFFFFu, p0, o);
                float e0 = p0 + c1 + s2d; e0 = (e0 > 0.f) ? e0 : 0.2f * e0;
                float x0 = __expf(e0);
                den += x0; ax += x0 * f0.x; ay += x0 * f0.y;
            }
        }
        float inv = 1.f / (den + 1e-9f);
        float sden = den * inv;
        __syncwarp();
        sg[wid][2 * lane] = ax * inv;
        sg[wid][2 * lane + 1] = ay * inv;
        __syncwarp();
        float n0 = sden * sb1[2 * lane], n1 = sden * sb1[2 * lane + 1];
        #pragma unroll 16
        for (int k = 0; k < D; k++) {
            float gk = sg[wid][k];
            float2 wr = ((const float2*)(sW1 + k * D))[lane];
            n0 += gk * wr.x; n1 += gk * wr.y;
        }
        float sum0 = hs.x + n0, sum1 = hs.y + n1;
        float p0s = hs.x * n0, p1s = hs.y * n1;
        __syncwarp();
        sg[wid][2 * lane] = p0s;
        sg[wid][2 * lane + 1] = p1s;
        __syncwarp();
        float z0 = sum0 + sb2[2 * lane], z1 = sum1 + sb2[2 * lane + 1];
        #pragma unroll 16
        for (int k = 0; k < D; k++) {
            float pk = sg[wid][k];
            float2 wr = ((const float2*)(sW2 + k * D))[lane];
            z0 += pk * wr.x; z1 += pk * wr.y;
        }
        float h0 = (z0 > 0.f) ? z0 : 0.2f * z0;
        float h1 = (z1 > 0.f) ? z1 : 0.2f * z1;
        float ss = h0 * h0 + h1 * h1;
        #pragma unroll
        for (int o = 16; o; o >>= 1) ss += __shfl_xor_sync(0xFFFFFFFFu, ss, o);
        float invn = 1.f / fmaxf(sqrtf(ss), 1e-12f);
        float* orow = g_hd + (size_t)q * D;
        orow[2 * lane] = h0 * invn;
        orow[2 * lane + 1] = h1 * invn;
    }
}

// -------- K4: final pair dots (dense h_out via slot map) --------
__global__ void k_final(const int* __restrict__ uid, const int* __restrict__ iid,
                        const float* __restrict__ ue, const float* __restrict__ ee,
                        float* __restrict__ out) {
    int lane = threadIdx.x & 31;
    int wg = (blockIdx.x * blockDim.x + threadIdx.x) >> 5;
    int nwarps = (gridDim.x * blockDim.x) >> 5;
    for (int p = wg; p < BATCH; p += nwarps) {
        int un = uid[p];
        int in = N_USERS + iid[p];
        float2 fu = feat2(un, ue, ee)[lane];
        float2 fi = feat2(in, ue, ee)[lane];
        float acc = fu.x * fi.x + fu.y * fi.y;
        int su = g_slot[un], si = g_slot[in];
        float2 hu = ((const float2*)(g_hd + (size_t)su * D))[lane];
        float2 hi = ((const float2*)(g_hd + (size_t)si * D))[lane];
        acc += hu.x * hi.x + hu.y * hi.y;
        #pragma unroll
        for (int o = 16; o; o >>= 1) acc += __shfl_xor_sync(0xFFFFFFFFu, acc, o);
        if (lane == 0) out[p] = acc;
    }
}

extern "C" void kernel_launch(void* const* d_in, const int* in_sizes, int n_in,
                              void* d_out, int out_size) {
    const int* idx = (const int*)d_in[0];
    const int* uid = (const int*)d_in[1];
    const int* iid = (const int*)d_in[2];
    int base = (in_sizes[3] <= 2) ? 4 : 3;   // skip num_nodes scalar if present
    const float* ue = (const float*)d_in[base + 0];
    const float* ee = (const float*)d_in[base + 1];
    const float* Wa = (const float*)d_in[base + 2];
    const float* ba = (const float*)d_in[base + 3];
    const float* W1 = (const float*)d_in[base + 4];
    const float* b1 = (const float*)d_in[base + 5];
    const float* W2 = (const float*)d_in[base + 6];
    const float* b2 = (const float*)d_in[base + 7];
    const float* a  = (const float*)d_in[base + 8];
    float* out = (float*)d_out;
    (void)n_in; (void)out_size;

    k_init<<<64, 256>>>(Wa, ba, a);
    k_mark<<<32, 256>>>(uid, iid);
    k_edge1<<<2048, 256>>>(idx);
    k_gather<<<1024, 256>>>(ue, ee, W1, b1, W2, b2);
    k_final<<<64, 256>>>(uid, iid, ue, ee, out);
}